// round 5
// baseline (speedup 1.0000x reference)
#include <cuda_runtime.h>
#include <cstdint>
#include <cstddef>

#define BSZ 16384
#define HSZ 1024

#define BM 128
#define BN 256
#define BK 32
#define NST 3
#define APAD 36                      /* padded row stride in floats */
#define A_FLOATS (BM * APAD)         /* 4608 */
#define B_FLOATS (BN * APAD)         /* 9216 */
#define STAGE_FLOATS (A_FLOATS + B_FLOATS)          /* 13824 */
#define BIAS_OFF (NST * STAGE_FLOATS)               /* 41472 */
#define SMEM_FLOATS (BIAS_OFF + BN)                 /* 41728 */
#define SMEM_BYTES (SMEM_FLOATS * 4)                /* 166912 */

__device__ __align__(16) float g_hr[(size_t)BSZ * HSZ];
__device__ __align__(16) float g_u [(size_t)BSZ * HSZ];
__device__ __align__(16) float g_gc[(size_t)BSZ * HSZ];

// ---------------- helpers (base-ISA only: sm_80-era PTX) ----------------
__device__ __forceinline__ uint32_t f2tf(float f) {
    uint32_t u;
    asm("cvt.rna.tf32.f32 %0, %1;" : "=r"(u) : "f"(f));
    return u;
}
__device__ __forceinline__ void cp16(void* dst_smem, const void* src) {
    uint32_t d = (uint32_t)__cvta_generic_to_shared(dst_smem);
    asm volatile("cp.async.cg.shared.global [%0], [%1], 16;" :: "r"(d), "l"(src));
}
__device__ __forceinline__ void cp_commit() {
    asm volatile("cp.async.commit_group;" ::: "memory");
}
__device__ __forceinline__ void cp_wait(int pending) {
    if (pending >= 2)      asm volatile("cp.async.wait_group 2;" ::: "memory");
    else if (pending == 1) asm volatile("cp.async.wait_group 1;" ::: "memory");
    else                   asm volatile("cp.async.wait_group 0;" ::: "memory");
}
__device__ __forceinline__ void mma_tf32(float* c, const uint32_t* a, uint32_t b0, uint32_t b1) {
    asm volatile(
        "mma.sync.aligned.m16n8k8.row.col.f32.tf32.tf32.f32 "
        "{%0,%1,%2,%3}, {%4,%5,%6,%7}, {%8,%9}, {%0,%1,%2,%3};"
        : "+f"(c[0]), "+f"(c[1]), "+f"(c[2]), "+f"(c[3])
        : "r"(a[0]), "r"(a[1]), "r"(a[2]), "r"(a[3]), "r"(b0), "r"(b1));
}
__device__ __forceinline__ float sigmf(float x) { return 1.0f / (1.0f + __expf(-x)); }
__device__ __forceinline__ float tanhfast(float x) { return 2.0f / (1.0f + __expf(-2.0f * x)) - 1.0f; }

// Issue one K-tile stage: A tile 128x32, B tile 256x32, both K-major fp32.
__device__ __forceinline__ void issue_stage(
    float* smem, int s, const float* Ak, const float* Bk, int tid)
{
    float* As = smem + s * STAGE_FLOATS;
    float* Bs = As + A_FLOATS;
    int r = tid >> 3, c4 = (tid & 7) * 4;
#pragma unroll
    for (int i = 0; i < 4; ++i) {
        int row = r + i * 32;
        cp16(As + row * APAD + c4, Ak + (size_t)row * HSZ + c4);
    }
#pragma unroll
    for (int i = 0; i < 8; ++i) {
        int row = r + i * 32;
        cp16(Bs + row * APAD + c4, Bk + (size_t)row * HSZ + c4);
    }
    cp_commit();
}

// Pipelined mainloop. A/B pointers pre-offset to (m0|n0, k=0). For KT=64 the
// second half of K comes from Ahi/Bhi (fused x|h vs W|U GEMM).
__device__ __forceinline__ void gemm_main(
    float* smem, float (&acc)[4][8][4],
    const float* Alo, const float* Ahi, const float* Blo, const float* Bhi,
    int KT, int tid, int wm, int wn, int g, int t)
{
#pragma unroll
    for (int i = 0; i < 4; ++i)
#pragma unroll
        for (int j = 0; j < 8; ++j)
#pragma unroll
            for (int k = 0; k < 4; ++k) acc[i][j][k] = 0.0f;

    // prologue: stages 0,1
#pragma unroll
    for (int f = 0; f < NST - 1; ++f) {
        const float* Ak = (f < 32) ? Alo + f * BK : Ahi + (f - 32) * BK;
        const float* Bk = (f < 32) ? Blo + f * BK : Bhi + (f - 32) * BK;
        issue_stage(smem, f % NST, Ak, Bk, tid);
    }

    for (int kt = 0; kt < KT; ++kt) {
        int nf = kt + NST - 1;
        if (nf < KT) {
            const float* Ak = (nf < 32) ? Alo + nf * BK : Ahi + (nf - 32) * BK;
            const float* Bk = (nf < 32) ? Blo + nf * BK : Bhi + (nf - 32) * BK;
            issue_stage(smem, nf % NST, Ak, Bk, tid);
        }
        cp_wait(min(NST - 1, KT - 1 - kt));
        __syncthreads();

        const float* As = smem + (kt % NST) * STAGE_FLOATS;
        const float* Bs = As + A_FLOATS;
#pragma unroll
        for (int kk = 0; kk < 4; ++kk) {
            int k0 = kk * 8 + t;
            uint32_t a[4][4];
#pragma unroll
            for (int ms = 0; ms < 4; ++ms) {
                int r0 = wm + ms * 16 + g;
                a[ms][0] = f2tf(As[r0 * APAD + k0]);
                a[ms][1] = f2tf(As[(r0 + 8) * APAD + k0]);
                a[ms][2] = f2tf(As[r0 * APAD + k0 + 4]);
                a[ms][3] = f2tf(As[(r0 + 8) * APAD + k0 + 4]);
            }
#pragma unroll
            for (int ns = 0; ns < 8; ++ns) {
                int c0 = wn + ns * 8 + g;
                uint32_t b0 = f2tf(Bs[c0 * APAD + k0]);
                uint32_t b1 = f2tf(Bs[c0 * APAD + k0 + 4]);
#pragma unroll
                for (int ms = 0; ms < 4; ++ms)
                    mma_tf32(acc[ms][ns], a[ms], b0, b1);
            }
        }
        __syncthreads();
    }
}

// ---------------- kernel 1: r, u gates and x@W^T + biases ----------------
__global__ void __launch_bounds__(256, 1) gru_k1(
    const float* __restrict__ x, const float* __restrict__ h,
    const float* __restrict__ Wr, const float* __restrict__ Ur,
    const float* __restrict__ Wu, const float* __restrict__ Uu,
    const float* __restrict__ W,
    const float* __restrict__ bWr, const float* __restrict__ bUr,
    const float* __restrict__ bWu, const float* __restrict__ bUu,
    const float* __restrict__ bW, const float* __restrict__ bU)
{
    extern __shared__ float smem[];
    int tid = threadIdx.x, wid = tid >> 5, lane = tid & 31;
    int g = lane >> 2, t = lane & 3;
    int wm = (wid >> 2) * 64, wn = (wid & 3) * 64;
    int gate = blockIdx.z;
    int m0 = blockIdx.y * BM, n0 = blockIdx.x * BN;
    int KT = (gate == 2) ? 32 : 64;

    const float *Blo, *Bhi, *b1, *b2;
    if (gate == 0)      { Blo = Wr; Bhi = Ur; b1 = bWr; b2 = bUr; }
    else if (gate == 1) { Blo = Wu; Bhi = Uu; b1 = bWu; b2 = bUu; }
    else                { Blo = W;  Bhi = W;  b1 = bW;  b2 = bU;  }

    smem[BIAS_OFF + tid] = b1[n0 + tid] + b2[n0 + tid];

    float acc[4][8][4];
    gemm_main(smem, acc,
              x + (size_t)m0 * HSZ, h + (size_t)m0 * HSZ,
              Blo + (size_t)n0 * HSZ, Bhi + (size_t)n0 * HSZ,
              KT, tid, wm, wn, g, t);

    const float* bs = smem + BIAS_OFF;
    float* outp = (gate == 0) ? g_hr : (gate == 1) ? g_u : g_gc;
#pragma unroll
    for (int ms = 0; ms < 4; ++ms) {
#pragma unroll
        for (int half = 0; half < 2; ++half) {
            size_t row = (size_t)(m0 + wm + ms * 16 + g + half * 8);
#pragma unroll
            for (int ns = 0; ns < 8; ++ns) {
                int col = wn + ns * 8 + 2 * t;
                float v0 = acc[ms][ns][half * 2 + 0] + bs[col + 0];
                float v1 = acc[ms][ns][half * 2 + 1] + bs[col + 1];
                size_t idx = row * HSZ + n0 + col;
                float2 o;
                if (gate == 0) {
                    float2 hv = *(const float2*)(h + idx);
                    o.x = hv.x * sigmf(v0);
                    o.y = hv.y * sigmf(v1);
                } else if (gate == 1) {
                    o.x = sigmf(v0);
                    o.y = sigmf(v1);
                } else {
                    o.x = v0;
                    o.y = v1;
                }
                *(float2*)(outp + idx) = o;
            }
        }
    }
}

// ---------------- kernel 2: (h*r)@U^T + final combine ----------------
__global__ void __launch_bounds__(256, 1) gru_k2(
    const float* __restrict__ U, const float* __restrict__ h,
    float* __restrict__ out)
{
    extern __shared__ float smem[];
    int tid = threadIdx.x, wid = tid >> 5, lane = tid & 31;
    int g = lane >> 2, t = lane & 3;
    int wm = (wid >> 2) * 64, wn = (wid & 3) * 64;
    int m0 = blockIdx.y * BM, n0 = blockIdx.x * BN;

    float acc[4][8][4];
    gemm_main(smem, acc,
              g_hr + (size_t)m0 * HSZ, g_hr + (size_t)m0 * HSZ,
              U + (size_t)n0 * HSZ, U + (size_t)n0 * HSZ,
              32, tid, wm, wn, g, t);

#pragma unroll
    for (int ms = 0; ms < 4; ++ms) {
#pragma unroll
        for (int half = 0; half < 2; ++half) {
            size_t row = (size_t)(m0 + wm + ms * 16 + g + half * 8);
#pragma unroll
            for (int ns = 0; ns < 8; ++ns) {
                int col = wn + ns * 8 + 2 * t;
                size_t idx = row * HSZ + n0 + col;
                float2 gc = *(const float2*)(g_gc + idx);
                float2 uu = *(const float2*)(g_u + idx);
                float2 hv = *(const float2*)(h + idx);
                float c0 = tanhfast(acc[ms][ns][half * 2 + 0] + gc.x);
                float c1 = tanhfast(acc[ms][ns][half * 2 + 1] + gc.y);
                float2 o;
                o.x = hv.x + uu.x * (c0 - hv.x);
                o.y = hv.y + uu.y * (c1 - hv.y);
                *(float2*)(out + idx) = o;
            }
        }
    }
}

// ---------------- host ----------------
extern "C" void kernel_launch(void* const* d_in, const int* in_sizes, int n_in,
                              void* d_out, int out_size) {
    (void)in_sizes; (void)n_in; (void)out_size;
    const float* x   = (const float*)d_in[0];
    const float* h   = (const float*)d_in[1];
    const float* Wr  = (const float*)d_in[2];
    const float* bWr = (const float*)d_in[3];
    const float* Ur  = (const float*)d_in[4];
    const float* bUr = (const float*)d_in[5];
    const float* Wu  = (const float*)d_in[6];
    const float* bWu = (const float*)d_in[7];
    const float* Uu  = (const float*)d_in[8];
    const float* bUu = (const float*)d_in[9];
    const float* W   = (const float*)d_in[10];
    const float* bW  = (const float*)d_in[11];
    const float* U   = (const float*)d_in[12];
    const float* bU  = (const float*)d_in[13];

    static int attr_done = 0;
    if (!attr_done) {
        cudaFuncSetAttribute(gru_k1, cudaFuncAttributeMaxDynamicSharedMemorySize, SMEM_BYTES);
        cudaFuncSetAttribute(gru_k2, cudaFuncAttributeMaxDynamicSharedMemorySize, SMEM_BYTES);
        attr_done = 1;
    }

    gru_k1<<<dim3(HSZ / BN, BSZ / BM, 3), 256, SMEM_BYTES>>>(
        x, h, Wr, Ur, Wu, Uu, W, bWr, bUr, bWu, bUu, bW, bU);
    gru_k2<<<dim3(HSZ / BN, BSZ / BM), 256, SMEM_BYTES>>>(U, h, (float*)d_out);
}

// round 6
// speedup vs baseline: 1.1529x; 1.1529x over previous
#include <cuda_runtime.h>
#include <cstdint>
#include <cstddef>

#define BSZ 16384
#define HSZ 1024

#define BM 128
#define BN 256
#define BK 32
#define NST 4
#define APAD 36                      /* padded row stride in floats */
#define A_FLOATS (BM * APAD)         /* 4608 */
#define B_FLOATS (BN * APAD)         /* 9216 */
#define STAGE_FLOATS (A_FLOATS + B_FLOATS)          /* 13824 */
#define BIAS_OFF (NST * STAGE_FLOATS)               /* 55296 */
#define SMEM_FLOATS (BIAS_OFF + BN)
#define SMEM_BYTES (SMEM_FLOATS * 4)                /* 222208 */

#define NTHREADS 512

// scratch: GEMM results + tf32-preconverted operands
__device__ __align__(16) float g_hr[(size_t)BSZ * HSZ];   // h*r, tf32-rounded
__device__ __align__(16) float g_u [(size_t)BSZ * HSZ];
__device__ __align__(16) float g_gc[(size_t)BSZ * HSZ];
__device__ __align__(16) float g_xt[(size_t)BSZ * HSZ];   // tf32(x)
__device__ __align__(16) float g_ht[(size_t)BSZ * HSZ];   // tf32(h)
__device__ __align__(16) float g_wt[6][(size_t)HSZ * HSZ]; // tf32(Wr,Ur,Wu,Uu,W,U)

// ---------------- helpers (base-ISA only) ----------------
__device__ __forceinline__ uint32_t f2tf(float f) {
    uint32_t u;
    asm("cvt.rna.tf32.f32 %0, %1;" : "=r"(u) : "f"(f));
    return u;
}
__device__ __forceinline__ void cp16(void* dst_smem, const void* src) {
    uint32_t d = (uint32_t)__cvta_generic_to_shared(dst_smem);
    asm volatile("cp.async.cg.shared.global [%0], [%1], 16;" :: "r"(d), "l"(src));
}
__device__ __forceinline__ void cp_commit() {
    asm volatile("cp.async.commit_group;" ::: "memory");
}
__device__ __forceinline__ void cp_wait(int pending) {
    if (pending >= 2)      asm volatile("cp.async.wait_group 2;" ::: "memory");
    else if (pending == 1) asm volatile("cp.async.wait_group 1;" ::: "memory");
    else                   asm volatile("cp.async.wait_group 0;" ::: "memory");
}
__device__ __forceinline__ void mma_tf32(float* c, const uint32_t* a, uint32_t b0, uint32_t b1) {
    asm volatile(
        "mma.sync.aligned.m16n8k8.row.col.f32.tf32.tf32.f32 "
        "{%0,%1,%2,%3}, {%4,%5,%6,%7}, {%8,%9}, {%0,%1,%2,%3};"
        : "+f"(c[0]), "+f"(c[1]), "+f"(c[2]), "+f"(c[3])
        : "r"(a[0]), "r"(a[1]), "r"(a[2]), "r"(a[3]), "r"(b0), "r"(b1));
}
__device__ __forceinline__ float sigmf(float x) { return 1.0f / (1.0f + __expf(-x)); }
__device__ __forceinline__ float tanhfast(float x) { return 2.0f / (1.0f + __expf(-2.0f * x)) - 1.0f; }

// ---------------- tf32 pre-convert (elementwise) ----------------
__global__ void __launch_bounds__(256) cvt_tf32(const float4* __restrict__ src,
                                                float4* __restrict__ dst, int n4) {
    int i = blockIdx.x * 256 + threadIdx.x;
    int stride = gridDim.x * 256;
    for (; i < n4; i += stride) {
        float4 v = src[i];
        float4 o;
        o.x = __uint_as_float(f2tf(v.x));
        o.y = __uint_as_float(f2tf(v.y));
        o.z = __uint_as_float(f2tf(v.z));
        o.w = __uint_as_float(f2tf(v.w));
        dst[i] = o;
    }
}

// Issue one K-tile stage: A tile 128x32, B tile 256x32, K-major fp32 (pre-tf32).
__device__ __forceinline__ void issue_stage(
    float* smem, int s, const float* Ak, const float* Bk, int tid)
{
    float* As = smem + s * STAGE_FLOATS;
    float* Bs = As + A_FLOATS;
    int r = tid >> 3, c4 = (tid & 7) * 4;   // r: 0..63
#pragma unroll
    for (int i = 0; i < 2; ++i) {
        int row = r + i * 64;
        cp16(As + row * APAD + c4, Ak + (size_t)row * HSZ + c4);
    }
#pragma unroll
    for (int i = 0; i < 4; ++i) {
        int row = r + i * 64;
        cp16(Bs + row * APAD + c4, Bk + (size_t)row * HSZ + c4);
    }
    cp_commit();
}

// Pipelined mainloop: NST stages, ONE __syncthreads per K-tile
// (issue-after-compute ordering; next-use of an overwritten stage is NST-1
// iterations away, protected by the intervening syncs).
// Warp tile 64x32: ms=4 (16-row steps), ns=4 (8-col steps). acc[4][4][4].
__device__ __forceinline__ void gemm_main(
    float* smem, float (&acc)[4][4][4],
    const float* Alo, const float* Ahi, const float* Blo, const float* Bhi,
    int KT, int tid, int wm, int wn, int g, int t)
{
#pragma unroll
    for (int i = 0; i < 4; ++i)
#pragma unroll
        for (int j = 0; j < 4; ++j)
#pragma unroll
            for (int k = 0; k < 4; ++k) acc[i][j][k] = 0.0f;

#pragma unroll
    for (int f = 0; f < NST - 1; ++f) {
        if (f < KT) {
            const float* Ak = (f < 32) ? Alo + f * BK : Ahi + (f - 32) * BK;
            const float* Bk = (f < 32) ? Blo + f * BK : Bhi + (f - 32) * BK;
            issue_stage(smem, f, Ak, Bk, tid);
        }
    }

    for (int kt = 0; kt < KT; ++kt) {
        cp_wait(min(NST - 2, KT - 1 - kt));
        __syncthreads();

        const float* As = smem + (kt % NST) * STAGE_FLOATS;
        const float* Bs = As + A_FLOATS;
#pragma unroll
        for (int kk = 0; kk < 4; ++kk) {
            int k0 = kk * 8 + t;
            uint32_t a[4][4];
#pragma unroll
            for (int ms = 0; ms < 4; ++ms) {
                int r0 = wm + ms * 16 + g;
                a[ms][0] = __float_as_uint(As[r0 * APAD + k0]);
                a[ms][1] = __float_as_uint(As[(r0 + 8) * APAD + k0]);
                a[ms][2] = __float_as_uint(As[r0 * APAD + k0 + 4]);
                a[ms][3] = __float_as_uint(As[(r0 + 8) * APAD + k0 + 4]);
            }
#pragma unroll
            for (int ns = 0; ns < 4; ++ns) {
                int c0 = wn + ns * 8 + g;
                uint32_t b0 = __float_as_uint(Bs[c0 * APAD + k0]);
                uint32_t b1 = __float_as_uint(Bs[c0 * APAD + k0 + 4]);
#pragma unroll
                for (int ms = 0; ms < 4; ++ms)
                    mma_tf32(acc[ms][ns], a[ms], b0, b1);
            }
        }

        int nf = kt + NST - 1;
        if (nf < KT) {
            const float* Ak = (nf < 32) ? Alo + nf * BK : Ahi + (nf - 32) * BK;
            const float* Bk = (nf < 32) ? Blo + nf * BK : Bhi + (nf - 32) * BK;
            issue_stage(smem, nf % NST, Ak, Bk, tid);
        }
    }
}

// ---------------- kernel 1: r, u gates and x@W^T + biases ----------------
__global__ void __launch_bounds__(NTHREADS, 1) gru_k1(
    const float* __restrict__ h,
    const float* __restrict__ bWr, const float* __restrict__ bUr,
    const float* __restrict__ bWu, const float* __restrict__ bUu,
    const float* __restrict__ bW, const float* __restrict__ bU)
{
    extern __shared__ float smem[];
    int tid = threadIdx.x, wid = tid >> 5, lane = tid & 31;
    int g = lane >> 2, t = lane & 3;
    int wm = (wid & 1) * 64, wn = (wid >> 1) * 32;
    int gate = blockIdx.z;
    int m0 = blockIdx.y * BM, n0 = blockIdx.x * BN;
    int KT = (gate == 2) ? 32 : 64;

    const float *Blo, *Bhi, *b1, *b2;
    if (gate == 0)      { Blo = g_wt[0]; Bhi = g_wt[1]; b1 = bWr; b2 = bUr; }
    else if (gate == 1) { Blo = g_wt[2]; Bhi = g_wt[3]; b1 = bWu; b2 = bUu; }
    else                { Blo = g_wt[4]; Bhi = g_wt[4]; b1 = bW;  b2 = bU;  }

    if (tid < BN) smem[BIAS_OFF + tid] = b1[n0 + tid] + b2[n0 + tid];

    float acc[4][4][4];
    gemm_main(smem, acc,
              g_xt + (size_t)m0 * HSZ, g_ht + (size_t)m0 * HSZ,
              Blo + (size_t)n0 * HSZ, Bhi + (size_t)n0 * HSZ,
              KT, tid, wm, wn, g, t);

    const float* bs = smem + BIAS_OFF;
#pragma unroll
    for (int ms = 0; ms < 4; ++ms) {
#pragma unroll
        for (int half = 0; half < 2; ++half) {
            size_t row = (size_t)(m0 + wm + ms * 16 + g + half * 8);
#pragma unroll
            for (int ns = 0; ns < 4; ++ns) {
                int col = wn + ns * 8 + 2 * t;
                float v0 = acc[ms][ns][half * 2 + 0] + bs[col + 0];
                float v1 = acc[ms][ns][half * 2 + 1] + bs[col + 1];
                size_t idx = row * HSZ + n0 + col;
                float2 o;
                if (gate == 0) {
                    // store h*r pre-rounded to tf32 (it is k2's GEMM A operand)
                    float2 hv = *(const float2*)(h + idx);
                    o.x = __uint_as_float(f2tf(hv.x * sigmf(v0)));
                    o.y = __uint_as_float(f2tf(hv.y * sigmf(v1)));
                    *(float2*)(g_hr + idx) = o;
                } else if (gate == 1) {
                    o.x = sigmf(v0);
                    o.y = sigmf(v1);
                    *(float2*)(g_u + idx) = o;
                } else {
                    o.x = v0;
                    o.y = v1;
                    *(float2*)(g_gc + idx) = o;
                }
            }
        }
    }
}

// ---------------- kernel 2: (h*r)@U^T + final combine ----------------
__global__ void __launch_bounds__(NTHREADS, 1) gru_k2(
    const float* __restrict__ h, float* __restrict__ out)
{
    extern __shared__ float smem[];
    int tid = threadIdx.x, wid = tid >> 5, lane = tid & 31;
    int g = lane >> 2, t = lane & 3;
    int wm = (wid & 1) * 64, wn = (wid >> 1) * 32;
    int m0 = blockIdx.y * BM, n0 = blockIdx.x * BN;

    float acc[4][4][4];
    gemm_main(smem, acc,
              g_hr + (size_t)m0 * HSZ, g_hr + (size_t)m0 * HSZ,
              g_wt[5] + (size_t)n0 * HSZ, g_wt[5] + (size_t)n0 * HSZ,
              32, tid, wm, wn, g, t);

#pragma unroll
    for (int ms = 0; ms < 4; ++ms) {
#pragma unroll
        for (int half = 0; half < 2; ++half) {
            size_t row = (size_t)(m0 + wm + ms * 16 + g + half * 8);
#pragma unroll
            for (int ns = 0; ns < 4; ++ns) {
                int col = wn + ns * 8 + 2 * t;
                size_t idx = row * HSZ + n0 + col;
                float2 gc = *(const float2*)(g_gc + idx);
                float2 uu = *(const float2*)(g_u + idx);
                float2 hv = *(const float2*)(h + idx);
                float c0 = tanhfast(acc[ms][ns][half * 2 + 0] + gc.x);
                float c1 = tanhfast(acc[ms][ns][half * 2 + 1] + gc.y);
                float2 o;
                o.x = hv.x + uu.x * (c0 - hv.x);
                o.y = hv.y + uu.y * (c1 - hv.y);
                *(float2*)(out + idx) = o;
            }
        }
    }
}

// ---------------- host ----------------
extern "C" void kernel_launch(void* const* d_in, const int* in_sizes, int n_in,
                              void* d_out, int out_size) {
    (void)in_sizes; (void)n_in; (void)out_size;
    const float* x   = (const float*)d_in[0];
    const float* h   = (const float*)d_in[1];
    const float* Wr  = (const float*)d_in[2];
    const float* bWr = (const float*)d_in[3];
    const float* Ur  = (const float*)d_in[4];
    const float* bUr = (const float*)d_in[5];
    const float* Wu  = (const float*)d_in[6];
    const float* bWu = (const float*)d_in[7];
    const float* Uu  = (const float*)d_in[8];
    const float* bUu = (const float*)d_in[9];
    const float* W   = (const float*)d_in[10];
    const float* bW  = (const float*)d_in[11];
    const float* U   = (const float*)d_in[12];
    const float* bU  = (const float*)d_in[13];

    cudaFuncSetAttribute(gru_k1, cudaFuncAttributeMaxDynamicSharedMemorySize, SMEM_BYTES);
    cudaFuncSetAttribute(gru_k2, cudaFuncAttributeMaxDynamicSharedMemorySize, SMEM_BYTES);

    float *xt, *ht, *wt;
    cudaGetSymbolAddress((void**)&xt, g_xt);
    cudaGetSymbolAddress((void**)&ht, g_ht);
    cudaGetSymbolAddress((void**)&wt, g_wt);

    const int big4 = (BSZ * HSZ) / 4;   // 4M float4
    const int w4   = (HSZ * HSZ) / 4;   // 256K float4
    cvt_tf32<<<1184, 256>>>((const float4*)x, (float4*)xt, big4);
    cvt_tf32<<<1184, 256>>>((const float4*)h, (float4*)ht, big4);
    cvt_tf32<<<296, 256>>>((const float4*)Wr, (float4*)(wt + 0 * (size_t)HSZ * HSZ), w4);
    cvt_tf32<<<296, 256>>>((const float4*)Ur, (float4*)(wt + 1 * (size_t)HSZ * HSZ), w4);
    cvt_tf32<<<296, 256>>>((const float4*)Wu, (float4*)(wt + 2 * (size_t)HSZ * HSZ), w4);
    cvt_tf32<<<296, 256>>>((const float4*)Uu, (float4*)(wt + 3 * (size_t)HSZ * HSZ), w4);
    cvt_tf32<<<296, 256>>>((const float4*)W,  (float4*)(wt + 4 * (size_t)HSZ * HSZ), w4);
    cvt_tf32<<<296, 256>>>((const float4*)U,  (float4*)(wt + 5 * (size_t)HSZ * HSZ), w4);

    gru_k1<<<dim3(HSZ / BN, BSZ / BM, 3), NTHREADS, SMEM_BYTES>>>(
        h, bWr, bUr, bWu, bUu, bW, bU);
    gru_k2<<<dim3(HSZ / BN, BSZ / BM), NTHREADS, SMEM_BYTES>>>(h, (float*)d_out);
}

// round 7
// speedup vs baseline: 1.1911x; 1.0332x over previous
#include <cuda_runtime.h>
#include <cstdint>
#include <cstddef>

#define BSZ 16384
#define HSZ 1024

#define BM 128
#define BN 256
#define BK 32
#define NST 4
#define APAD 36                      /* padded row stride in floats */
#define A_FLOATS (BM * APAD)         /* 4608 */
#define B_FLOATS (BN * APAD)         /* 9216 */
#define STAGE_FLOATS (A_FLOATS + B_FLOATS)          /* 13824 */
#define BIAS_OFF (NST * STAGE_FLOATS)               /* 55296 */
#define SMEM_FLOATS (BIAS_OFF + BN)
#define SMEM_BYTES (SMEM_FLOATS * 4)                /* 222208 */

#define NTHREADS 512

// scratch: GEMM results + tf32-preconverted weights
__device__ __align__(16) float g_hr[(size_t)BSZ * HSZ];   // h*r, tf32-rounded
__device__ __align__(16) float g_u [(size_t)BSZ * HSZ];
__device__ __align__(16) float g_gc[(size_t)BSZ * HSZ];
__device__ __align__(16) float g_wt[6][(size_t)HSZ * HSZ]; // tf32(Wr,Ur,Wu,Uu,W,U)

// ---------------- helpers (base-ISA only) ----------------
__device__ __forceinline__ uint32_t f2tf(float f) {
    uint32_t u;
    asm("cvt.rna.tf32.f32 %0, %1;" : "=r"(u) : "f"(f));
    return u;
}
__device__ __forceinline__ void cp16(void* dst_smem, const void* src) {
    uint32_t d = (uint32_t)__cvta_generic_to_shared(dst_smem);
    asm volatile("cp.async.cg.shared.global [%0], [%1], 16;" :: "r"(d), "l"(src));
}
__device__ __forceinline__ void cp_commit() {
    asm volatile("cp.async.commit_group;" ::: "memory");
}
__device__ __forceinline__ void cp_wait(int pending) {
    if (pending >= 2)      asm volatile("cp.async.wait_group 2;" ::: "memory");
    else if (pending == 1) asm volatile("cp.async.wait_group 1;" ::: "memory");
    else                   asm volatile("cp.async.wait_group 0;" ::: "memory");
}
__device__ __forceinline__ void mma_tf32(float* c, const uint32_t* a, uint32_t b0, uint32_t b1) {
    asm volatile(
        "mma.sync.aligned.m16n8k8.row.col.f32.tf32.tf32.f32 "
        "{%0,%1,%2,%3}, {%4,%5,%6,%7}, {%8,%9}, {%0,%1,%2,%3};"
        : "+f"(c[0]), "+f"(c[1]), "+f"(c[2]), "+f"(c[3])
        : "r"(a[0]), "r"(a[1]), "r"(a[2]), "r"(a[3]), "r"(b0), "r"(b1));
}
__device__ __forceinline__ float sigmf(float x) { return 1.0f / (1.0f + __expf(-x)); }
__device__ __forceinline__ float tanhfast(float x) { return 2.0f / (1.0f + __expf(-2.0f * x)) - 1.0f; }

// ---------------- one-shot tf32 pre-convert of all 6 weight matrices ------
__global__ void __launch_bounds__(256) cvt_w(
    const float4* __restrict__ s0, const float4* __restrict__ s1,
    const float4* __restrict__ s2, const float4* __restrict__ s3,
    const float4* __restrict__ s4, const float4* __restrict__ s5)
{
    const int n4 = (HSZ * HSZ) / 4;
    float4* dst = (float4*)g_wt;
    int stride = gridDim.x * 256;
    for (int i = blockIdx.x * 256 + threadIdx.x; i < 6 * n4; i += stride) {
        int seg = i / n4, off = i - seg * n4;
        const float4* s = (seg == 0) ? s0 : (seg == 1) ? s1 : (seg == 2) ? s2
                        : (seg == 3) ? s3 : (seg == 4) ? s4 : s5;
        float4 v = s[off];
        float4 o;
        o.x = __uint_as_float(f2tf(v.x));
        o.y = __uint_as_float(f2tf(v.y));
        o.z = __uint_as_float(f2tf(v.z));
        o.w = __uint_as_float(f2tf(v.w));
        dst[i] = o;
    }
}

// Issue one K-tile stage: A tile 128x32, B tile 256x32, K-major fp32.
__device__ __forceinline__ void issue_stage(
    float* smem, int s, const float* Ak, const float* Bk, int tid)
{
    float* As = smem + s * STAGE_FLOATS;
    float* Bs = As + A_FLOATS;
    int r = tid >> 3, c4 = (tid & 7) * 4;   // r: 0..63
#pragma unroll
    for (int i = 0; i < 2; ++i) {
        int row = r + i * 64;
        cp16(As + row * APAD + c4, Ak + (size_t)row * HSZ + c4);
    }
#pragma unroll
    for (int i = 0; i < 4; ++i) {
        int row = r + i * 64;
        cp16(Bs + row * APAD + c4, Bk + (size_t)row * HSZ + c4);
    }
    cp_commit();
}

// Load the 16 A-fragment registers for one k0 column group.
// CVTA: apply cvt.rna.tf32 (k1: raw x/h inputs). Otherwise bits pass through.
template <bool CVTA>
__device__ __forceinline__ void load_afrag(
    const float* As, int wm, int g, int k0, uint32_t (&a)[4][4])
{
#pragma unroll
    for (int ms = 0; ms < 4; ++ms) {
        int r0 = wm + ms * 16 + g;
        float f0 = As[r0 * APAD + k0];
        float f1 = As[(r0 + 8) * APAD + k0];
        float f2 = As[r0 * APAD + k0 + 4];
        float f3 = As[(r0 + 8) * APAD + k0 + 4];
        if (CVTA) {
            a[ms][0] = f2tf(f0); a[ms][1] = f2tf(f1);
            a[ms][2] = f2tf(f2); a[ms][3] = f2tf(f3);
        } else {
            a[ms][0] = __float_as_uint(f0); a[ms][1] = __float_as_uint(f1);
            a[ms][2] = __float_as_uint(f2); a[ms][3] = __float_as_uint(f3);
        }
    }
}

// Pipelined mainloop: NST cp.async stages, ONE __syncthreads per K-tile,
// explicit A-fragment double buffering across kk-steps.
// Warp tile 64x32: ms=4 (16-row steps), ns=4 (8-col steps). acc[4][4][4].
template <bool CVTA>
__device__ __forceinline__ void gemm_main(
    float* smem, float (&acc)[4][4][4],
    const float* Alo, const float* Ahi, const float* Blo, const float* Bhi,
    int KT, int tid, int wm, int wn, int g, int t)
{
#pragma unroll
    for (int i = 0; i < 4; ++i)
#pragma unroll
        for (int j = 0; j < 4; ++j)
#pragma unroll
            for (int k = 0; k < 4; ++k) acc[i][j][k] = 0.0f;

#pragma unroll
    for (int f = 0; f < NST - 1; ++f) {
        if (f < KT) {
            const float* Ak = (f < 32) ? Alo + f * BK : Ahi + (f - 32) * BK;
            const float* Bk = (f < 32) ? Blo + f * BK : Bhi + (f - 32) * BK;
            issue_stage(smem, f, Ak, Bk, tid);
        }
    }

    for (int kt = 0; kt < KT; ++kt) {
        cp_wait(min(NST - 2, KT - 1 - kt));
        __syncthreads();

        const float* As = smem + (kt % NST) * STAGE_FLOATS;
        const float* Bs = As + A_FLOATS;

        uint32_t aP[4][4], aQ[4][4];
        load_afrag<CVTA>(As, wm, g, t, aP);
#pragma unroll
        for (int kk = 0; kk < 4; ++kk) {
            uint32_t (&cur)[4][4] = (kk & 1) ? aQ : aP;
            uint32_t (&nxt)[4][4] = (kk & 1) ? aP : aQ;
            if (kk < 3)
                load_afrag<CVTA>(As, wm, g, (kk + 1) * 8 + t, nxt);
            int k0 = kk * 8 + t;
#pragma unroll
            for (int ns = 0; ns < 4; ++ns) {
                int c0 = wn + ns * 8 + g;
                uint32_t b0 = __float_as_uint(Bs[c0 * APAD + k0]);
                uint32_t b1 = __float_as_uint(Bs[c0 * APAD + k0 + 4]);
#pragma unroll
                for (int ms = 0; ms < 4; ++ms)
                    mma_tf32(acc[ms][ns], cur[ms], b0, b1);
            }
        }

        int nf = kt + NST - 1;
        if (nf < KT) {
            const float* Ak = (nf < 32) ? Alo + nf * BK : Ahi + (nf - 32) * BK;
            const float* Bk = (nf < 32) ? Blo + nf * BK : Bhi + (nf - 32) * BK;
            issue_stage(smem, nf % NST, Ak, Bk, tid);
        }
    }
}

// ---------------- kernel 1: r, u gates and x@W^T + biases ----------------
__global__ void __launch_bounds__(NTHREADS, 1) gru_k1(
    const float* __restrict__ x, const float* __restrict__ h,
    const float* __restrict__ bWr, const float* __restrict__ bUr,
    const float* __restrict__ bWu, const float* __restrict__ bUu,
    const float* __restrict__ bW, const float* __restrict__ bU)
{
    extern __shared__ float smem[];
    int tid = threadIdx.x, wid = tid >> 5, lane = tid & 31;
    int g = lane >> 2, t = lane & 3;
    int wm = (wid & 1) * 64, wn = (wid >> 1) * 32;
    int gate = blockIdx.z;
    int m0 = blockIdx.y * BM, n0 = blockIdx.x * BN;
    int KT = (gate == 2) ? 32 : 64;

    const float *Blo, *Bhi, *b1, *b2;
    if (gate == 0)      { Blo = g_wt[0]; Bhi = g_wt[1]; b1 = bWr; b2 = bUr; }
    else if (gate == 1) { Blo = g_wt[2]; Bhi = g_wt[3]; b1 = bWu; b2 = bUu; }
    else                { Blo = g_wt[4]; Bhi = g_wt[4]; b1 = bW;  b2 = bU;  }

    if (tid < BN) smem[BIAS_OFF + tid] = b1[n0 + tid] + b2[n0 + tid];

    float acc[4][4][4];
    gemm_main<true>(smem, acc,
              x + (size_t)m0 * HSZ, h + (size_t)m0 * HSZ,
              Blo + (size_t)n0 * HSZ, Bhi + (size_t)n0 * HSZ,
              KT, tid, wm, wn, g, t);

    const float* bs = smem + BIAS_OFF;
#pragma unroll
    for (int ms = 0; ms < 4; ++ms) {
#pragma unroll
        for (int half = 0; half < 2; ++half) {
            size_t row = (size_t)(m0 + wm + ms * 16 + g + half * 8);
#pragma unroll
            for (int ns = 0; ns < 4; ++ns) {
                int col = wn + ns * 8 + 2 * t;
                float v0 = acc[ms][ns][half * 2 + 0] + bs[col + 0];
                float v1 = acc[ms][ns][half * 2 + 1] + bs[col + 1];
                size_t idx = row * HSZ + n0 + col;
                float2 o;
                if (gate == 0) {
                    // store h*r pre-rounded to tf32 (it is k2's GEMM A operand)
                    float2 hv = *(const float2*)(h + idx);
                    o.x = __uint_as_float(f2tf(hv.x * sigmf(v0)));
                    o.y = __uint_as_float(f2tf(hv.y * sigmf(v1)));
                    *(float2*)(g_hr + idx) = o;
                } else if (gate == 1) {
                    o.x = sigmf(v0);
                    o.y = sigmf(v1);
                    *(float2*)(g_u + idx) = o;
                } else {
                    o.x = v0;
                    o.y = v1;
                    *(float2*)(g_gc + idx) = o;
                }
            }
        }
    }
}

// ---------------- kernel 2: (h*r)@U^T + final combine ----------------
__global__ void __launch_bounds__(NTHREADS, 1) gru_k2(
    const float* __restrict__ h, float* __restrict__ out)
{
    extern __shared__ float smem[];
    int tid = threadIdx.x, wid = tid >> 5, lane = tid & 31;
    int g = lane >> 2, t = lane & 3;
    int wm = (wid & 1) * 64, wn = (wid >> 1) * 32;
    int m0 = blockIdx.y * BM, n0 = blockIdx.x * BN;

    float acc[4][4][4];
    gemm_main<false>(smem, acc,
              g_hr + (size_t)m0 * HSZ, g_hr + (size_t)m0 * HSZ,
              g_wt[5] + (size_t)n0 * HSZ, g_wt[5] + (size_t)n0 * HSZ,
              32, tid, wm, wn, g, t);

#pragma unroll
    for (int ms = 0; ms < 4; ++ms) {
#pragma unroll
        for (int half = 0; half < 2; ++half) {
            size_t row = (size_t)(m0 + wm + ms * 16 + g + half * 8);
#pragma unroll
            for (int ns = 0; ns < 4; ++ns) {
                int col = wn + ns * 8 + 2 * t;
                size_t idx = row * HSZ + n0 + col;
                float2 gc = *(const float2*)(g_gc + idx);
                float2 uu = *(const float2*)(g_u + idx);
                float2 hv = *(const float2*)(h + idx);
                float c0 = tanhfast(acc[ms][ns][half * 2 + 0] + gc.x);
                float c1 = tanhfast(acc[ms][ns][half * 2 + 1] + gc.y);
                float2 o;
                o.x = hv.x + uu.x * (c0 - hv.x);
                o.y = hv.y + uu.y * (c1 - hv.y);
                *(float2*)(out + idx) = o;
            }
        }
    }
}

// ---------------- host ----------------
extern "C" void kernel_launch(void* const* d_in, const int* in_sizes, int n_in,
                              void* d_out, int out_size) {
    (void)in_sizes; (void)n_in; (void)out_size;
    const float* x   = (const float*)d_in[0];
    const float* h   = (const float*)d_in[1];
    const float* Wr  = (const float*)d_in[2];
    const float* bWr = (const float*)d_in[3];
    const float* Ur  = (const float*)d_in[4];
    const float* bUr = (const float*)d_in[5];
    const float* Wu  = (const float*)d_in[6];
    const float* bWu = (const float*)d_in[7];
    const float* Uu  = (const float*)d_in[8];
    const float* bUu = (const float*)d_in[9];
    const float* W   = (const float*)d_in[10];
    const float* bW  = (const float*)d_in[11];
    const float* U   = (const float*)d_in[12];
    const float* bU  = (const float*)d_in[13];

    cudaFuncSetAttribute(gru_k1, cudaFuncAttributeMaxDynamicSharedMemorySize, SMEM_BYTES);
    cudaFuncSetAttribute(gru_k2, cudaFuncAttributeMaxDynamicSharedMemorySize, SMEM_BYTES);

    cvt_w<<<2048, 256>>>((const float4*)Wr, (const float4*)Ur,
                         (const float4*)Wu, (const float4*)Uu,
                         (const float4*)W,  (const float4*)U);

    gru_k1<<<dim3(HSZ / BN, BSZ / BM, 3), NTHREADS, SMEM_BYTES>>>(
        x, h, bWr, bUr, bWu, bUu, bW, bU);
    gru_k2<<<dim3(HSZ / BN, BSZ / BM), NTHREADS, SMEM_BYTES>>>(h, (float*)d_out);
}